// round 2
// baseline (speedup 1.0000x reference)
#include <cuda_runtime.h>
#include <cstdint>

// ---------------- Problem constants ----------------
#define EMAX 100000
#define NNMAX 20000
#define BMAX 16
#define URED 256
#define USZ 4096
#define EIN_DIM 275     // 9 + 9 + 1 + 256
#define EH 1024
#define EOUT 512
#define NIN_DIM 521     // 9 + 512
#define NH 512
#define MIN_DIM 777     // 9 + 512 + 256

// ---------------- Scratch (static device globals; no runtime alloc) ----------------
__device__ float g_ur[BMAX * URED];
__device__ float g_ein[(size_t)EMAX * EIN_DIM];
__device__ float g_h1[(size_t)EMAX * EH];
__device__ float g_h2[(size_t)EMAX * EH];
__device__ float g_nin[(size_t)EMAX * NIN_DIM];
__device__ float g_agg[(size_t)NNMAX * NH];
__device__ float g_cnt[NNMAX];
__device__ float g_min[(size_t)NNMAX * MIN_DIM];
__device__ int   g_is64;

// ---------------- Index dtype detection ----------------
__global__ void k_init_flag() { g_is64 = 1; }

// Reads n int64 interpretations. Safe for both dtypes when n = elem_count/2.
__global__ void k_detect(const long long* __restrict__ p, int n, long long maxv) {
    int i = blockIdx.x * blockDim.x + threadIdx.x;
    if (i < n) {
        long long v = p[i];
        if (v < 0 || v >= maxv) g_is64 = 0;
    }
}

__device__ __forceinline__ long long ld_idx(const void* p, long long i) {
    if (g_is64) return ((const long long*)p)[i];
    return (long long)((const int*)p)[i];
}

// ---------------- u reduction: g_ur[b][j] = dot(u[b], w_sel[j]) + b_sel[j] ----------------
__global__ void k_ur(const float* __restrict__ u, const float* __restrict__ w,
                     const float* __restrict__ bias, int B) {
    int wid = (blockIdx.x * blockDim.x + threadIdx.x) >> 5;
    int lane = threadIdx.x & 31;
    if (wid >= B * URED) return;
    int b = wid >> 8;           // /256
    int j = wid & 255;
    const float* up = u + (size_t)b * USZ;
    const float* wp = w + (size_t)j * USZ;
    float s = 0.f;
    for (int k = lane; k < USZ; k += 32) s += up[k] * wp[k];
    #pragma unroll
    for (int o = 16; o; o >>= 1) s += __shfl_down_sync(0xffffffffu, s, o);
    if (lane == 0) g_ur[wid] = s + bias[j];
}

// ---------------- edge input concat: [x[row], x[col], ea, u_r[batch[row]]] ----------------
__global__ void k_econcat(const float* __restrict__ x, const void* __restrict__ eidx,
                          const float* __restrict__ ea, const void* __restrict__ batch,
                          int E) {
    int e = (blockIdx.x * blockDim.x + threadIdx.x) >> 5;
    int lane = threadIdx.x & 31;
    if (e >= E) return;
    long long row = ld_idx(eidx, e);
    long long col = ld_idx(eidx, (long long)E + e);
    long long b = ld_idx(batch, row);
    float* o = g_ein + (size_t)e * EIN_DIM;
    if (lane < 9)                o[lane] = x[row * 9 + lane];
    else if (lane < 18)          o[lane] = x[col * 9 + (lane - 9)];
    else if (lane == 18)         o[18]   = ea[e];
    const float* ur = g_ur + b * URED;
    for (int j = lane; j < URED; j += 32) o[19 + j] = ur[j];
}

// ---------------- node input concat: [x[col], edge_out] ----------------
__global__ void k_nconcat(const float* __restrict__ x, const void* __restrict__ eidx,
                          const float* __restrict__ eout, int E) {
    int e = (blockIdx.x * blockDim.x + threadIdx.x) >> 5;
    int lane = threadIdx.x & 31;
    if (e >= E) return;
    long long col = ld_idx(eidx, (long long)E + e);
    float* o = g_nin + (size_t)e * NIN_DIM;
    if (lane < 9) o[lane] = x[col * 9 + lane];
    const float* ep = eout + (size_t)e * EOUT;
    for (int j = lane; j < EOUT; j += 32) o[9 + j] = ep[j];
}

// ---------------- tiled SGEMM: C[M,N] = act(A[M,K] @ W[N,K]^T + bias) ----------------
#define BM 128
#define BN 128
#define BK 8
#define TM 8
#define TN 8

template <bool RELU>
__global__ void k_sgemm(const float* __restrict__ A, const float* __restrict__ W,
                        const float* __restrict__ bias, float* __restrict__ C,
                        int M, int N, int K) {
    __shared__ float As[BK][BM];
    __shared__ float Ws[BK][BN];
    const int tid = threadIdx.x;                 // 256 threads
    const int bm = blockIdx.y * BM;
    const int bn = blockIdx.x * BN;
    const int trow = tid >> 4;                   // 0..15 (M dir)
    const int tcol = tid & 15;                   // 0..15 (N dir)

    const int l_r = tid >> 1;                    // 0..127
    const int l_k = (tid & 1) * 4;               // 0 or 4

    float acc[TM][TN];
    #pragma unroll
    for (int i = 0; i < TM; i++)
        #pragma unroll
        for (int j = 0; j < TN; j++) acc[i][j] = 0.f;

    for (int k0 = 0; k0 < K; k0 += BK) {
        // load A tile [BM x BK] -> As[k][m]
        {
            int m = bm + l_r;
            #pragma unroll
            for (int i = 0; i < 4; i++) {
                int k = k0 + l_k + i;
                As[l_k + i][l_r] = (m < M && k < K) ? A[(long long)m * K + k] : 0.f;
            }
        }
        // load W tile [BN x BK] -> Ws[k][n]
        {
            int n = bn + l_r;
            #pragma unroll
            for (int i = 0; i < 4; i++) {
                int k = k0 + l_k + i;
                Ws[l_k + i][l_r] = (n < N && k < K) ? W[(long long)n * K + k] : 0.f;
            }
        }
        __syncthreads();
        #pragma unroll
        for (int kk = 0; kk < BK; kk++) {
            float ra[TM], rb[TN];
            #pragma unroll
            for (int i = 0; i < TM; i++) ra[i] = As[kk][trow * TM + i];
            #pragma unroll
            for (int j = 0; j < TN; j++) rb[j] = Ws[kk][tcol * TN + j];
            #pragma unroll
            for (int i = 0; i < TM; i++)
                #pragma unroll
                for (int j = 0; j < TN; j++)
                    acc[i][j] += ra[i] * rb[j];
        }
        __syncthreads();
    }

    #pragma unroll
    for (int i = 0; i < TM; i++) {
        int m = bm + trow * TM + i;
        if (m >= M) continue;
        #pragma unroll
        for (int j = 0; j < TN; j++) {
            int n = bn + tcol * TN + j;
            if (n >= N) continue;
            float v = acc[i][j] + bias[n];
            if (RELU) v = v > 0.f ? v : 0.f;
            C[(long long)m * N + n] = v;
        }
    }
}

// ---------------- zero fill ----------------
__global__ void k_zero(float* p, int n) {
    int i = blockIdx.x * blockDim.x + threadIdx.x;
    if (i < n) p[i] = 0.f;
}

// ---------------- scatter-add node features + counts ----------------
__global__ void k_scatter(const float* __restrict__ h, const void* __restrict__ eidx, int E) {
    int e = (blockIdx.x * blockDim.x + threadIdx.x) >> 5;
    int lane = threadIdx.x & 31;
    if (e >= E) return;
    long long r = ld_idx(eidx, e);
    float* a = g_agg + (size_t)r * NH;
    const float* hp = h + (size_t)e * NH;
    for (int j = lane; j < NH; j += 32) atomicAdd(&a[j], hp[j]);
    if (lane == 0) atomicAdd(&g_cnt[r], 1.f);
}

// ---------------- final node concat: [x, agg/cnt, u_r[batch]] ----------------
__global__ void k_mconcat(const float* __restrict__ x, const void* __restrict__ batch, int Nn) {
    int n = (blockIdx.x * blockDim.x + threadIdx.x) >> 5;
    int lane = threadIdx.x & 31;
    if (n >= Nn) return;
    float* o = g_min + (size_t)n * MIN_DIM;
    if (lane < 9) o[lane] = x[(size_t)n * 9 + lane];
    float c = g_cnt[n];
    float inv = 1.f / (c < 1.f ? 1.f : c);
    const float* a = g_agg + (size_t)n * NH;
    for (int j = lane; j < NH; j += 32) o[9 + j] = a[j] * inv;
    long long b = ld_idx(batch, n);
    const float* ur = g_ur + b * URED;
    for (int j = lane; j < URED; j += 32) o[9 + NH + j] = ur[j];
}

// ---------------- final 512 -> 1 dot ----------------
__global__ void k_final(const float* __restrict__ h, const float* __restrict__ w,
                        const float* __restrict__ bias, float* __restrict__ out, int Nn) {
    int n = (blockIdx.x * blockDim.x + threadIdx.x) >> 5;
    int lane = threadIdx.x & 31;
    if (n >= Nn) return;
    const float* hp = h + (size_t)n * NH;
    float s = 0.f;
    for (int k = lane; k < NH; k += 32) s += hp[k] * w[k];
    #pragma unroll
    for (int o = 16; o; o >>= 1) s += __shfl_down_sync(0xffffffffu, s, o);
    if (lane == 0) out[n] = s + bias[0];
}

// ---------------- host helpers ----------------
static float* sym(const void* s) {
    void* p = nullptr;
    cudaGetSymbolAddress(&p, s);
    return (float*)p;
}

static void run_gemm(const float* A, const float* W, const float* bias, float* C,
                     int M, int N, int K, bool relu) {
    dim3 grid((N + BN - 1) / BN, (M + BM - 1) / BM);
    if (relu) k_sgemm<true><<<grid, 256>>>(A, W, bias, C, M, N, K);
    else      k_sgemm<false><<<grid, 256>>>(A, W, bias, C, M, N, K);
}

extern "C" void kernel_launch(void* const* d_in, const int* in_sizes, int n_in,
                              void* d_out, int out_size) {
    const float* x    = (const float*)d_in[0];
    const void*  eidx = d_in[1];
    const float* ea   = (const float*)d_in[2];
    const float* u    = (const float*)d_in[3];
    const void*  bat  = d_in[4];
    const float* w_sel = (const float*)d_in[5];
    const float* b_sel = (const float*)d_in[6];
    const float* ew0 = (const float*)d_in[7];  const float* eb0 = (const float*)d_in[8];
    const float* ew1 = (const float*)d_in[9];  const float* eb1 = (const float*)d_in[10];
    const float* ew2 = (const float*)d_in[11]; const float* eb2 = (const float*)d_in[12];
    const float* ew3 = (const float*)d_in[13]; const float* eb3 = (const float*)d_in[14];
    const float* ew4 = (const float*)d_in[15]; const float* eb4 = (const float*)d_in[16];
    const float* nw0 = (const float*)d_in[17]; const float* nb0 = (const float*)d_in[18];
    const float* nw1 = (const float*)d_in[19]; const float* nb1 = (const float*)d_in[20];
    const float* mw0 = (const float*)d_in[21]; const float* mb0 = (const float*)d_in[22];
    const float* mw1 = (const float*)d_in[23]; const float* mb1 = (const float*)d_in[24];
    float* out = (float*)d_out;

    const int Nn = in_sizes[0] / 9;      // 20000
    const int E  = in_sizes[1] / 2;      // 100000 (element count same for i32/i64)
    const int B  = in_sizes[3] / USZ;    // 16

    float* p_ur  = sym(g_ur);
    float* p_ein = sym(g_ein);
    float* p_h1  = sym(g_h1);
    float* p_h2  = sym(g_h2);
    float* p_nin = sym(g_nin);
    float* p_agg = sym(g_agg);
    float* p_cnt = sym(g_cnt);
    float* p_min = sym(g_min);

    // 0. dtype detection for edge_index/batch (int64 vs int32)
    k_init_flag<<<1, 1>>>();
    k_detect<<<(E + 255) / 256, 256>>>((const long long*)eidx, E, (long long)Nn);

    // 1. u_r = u @ w_sel^T + b_sel
    k_ur<<<(B * URED * 32 + 255) / 256, 256>>>(u, w_sel, b_sel, B);

    // 2. edge input concat
    k_econcat<<<(E * 32 + 255) / 256, 256>>>(x, eidx, ea, bat, E);

    // 3. edge MLP 275->1024->1024->1024->1024->512
    run_gemm(p_ein, ew0, eb0, p_h1, E, EH, EIN_DIM, true);
    run_gemm(p_h1,  ew1, eb1, p_h2, E, EH, EH, true);
    run_gemm(p_h2,  ew2, eb2, p_h1, E, EH, EH, true);
    run_gemm(p_h1,  ew3, eb3, p_h2, E, EH, EH, true);
    run_gemm(p_h2,  ew4, eb4, p_h1, E, EOUT, EH, false);   // edge_out -> g_h1 (stride 512)

    // 4. node input concat [x[col], edge_out]
    k_nconcat<<<(E * 32 + 255) / 256, 256>>>(x, eidx, p_h1, E);

    // 5. node MLP1 521->512->512 (relu both)
    run_gemm(p_nin, nw0, nb0, p_h2, E, NH, NIN_DIM, true);
    run_gemm(p_h2,  nw1, nb1, p_h1, E, NH, NH, true);      // per-edge h -> g_h1

    // 6. scatter mean onto row
    k_zero<<<(Nn * NH + 255) / 256, 256>>>(p_agg, Nn * NH);
    k_zero<<<(Nn + 255) / 256, 256>>>(p_cnt, Nn);
    k_scatter<<<(E * 32 + 255) / 256, 256>>>(p_h1, eidx, E);

    // 7. final concat [x, agg, u_r[batch]]
    k_mconcat<<<(Nn * 32 + 255) / 256, 256>>>(x, bat, Nn);

    // 8. node MLP2 777->512 (relu) -> 1
    run_gemm(p_min, mw0, mb0, p_h2, Nn, NH, MIN_DIM, true);
    k_final<<<(Nn * 32 + 255) / 256, 256>>>(p_h2, mw1, mb1, out, Nn);
}

// round 5
// speedup vs baseline: 4.5962x; 4.5962x over previous
#include <cuda_runtime.h>
#include <cstdint>

// ---------------- Problem constants ----------------
#define EMAX 100000
#define NNMAX 20000
#define BMAX 16
#define URED 256
#define USZ 4096
#define EIN_DIM 275
#define EINP 288          // padded to x32
#define EH 1024
#define EOUT 512
#define NIN_DIM 521
#define NINP 544          // padded
#define NH 512
#define MIN_DIM 777
#define MINP 800          // padded

// ---------------- Scratch (static device globals) ----------------
__device__ float g_ur[BMAX * URED];
__device__ float g_ein[(size_t)EMAX * EINP];
__device__ float g_h1[(size_t)EMAX * EH];
__device__ float g_h2[(size_t)EMAX * EH];
__device__ float g_nin[(size_t)EMAX * NINP];
__device__ float g_agg[(size_t)NNMAX * NH];
__device__ float g_cnt[NNMAX];
__device__ float g_min[(size_t)NNMAX * MINP];
__device__ int   g_is64;

// repacked (tf32-rounded, zero-padded) weights
__device__ float g_w0[EH * EINP];
__device__ float g_w1[EH * EH];
__device__ float g_w2[EH * EH];
__device__ float g_w3[EH * EH];
__device__ float g_w4[EOUT * EH];
__device__ float g_wn0[NH * NINP];
__device__ float g_wn1[NH * NH];
__device__ float g_wm0[NH * MINP];

// ---------------- helpers ----------------
__device__ __forceinline__ float rtf32(float x) {
    uint32_t u;
    asm("cvt.rna.tf32.f32 %0, %1;" : "=r"(u) : "f"(x));
    return __uint_as_float(u);
}

__global__ void k_init_flag() { g_is64 = 1; }

__global__ void k_detect(const long long* __restrict__ p, int n, long long maxv) {
    int i = blockIdx.x * blockDim.x + threadIdx.x;
    if (i < n) {
        long long v = p[i];
        if (v < 0 || v >= maxv) g_is64 = 0;
    }
}

__device__ __forceinline__ long long ld_idx(const void* p, long long i) {
    if (g_is64) return ((const long long*)p)[i];
    return (long long)((const int*)p)[i];
}

// ---------------- weight repack: pad + tf32 round ----------------
__global__ void k_repack(const float* __restrict__ src, float* __restrict__ dst,
                         int Nr, int Kin, int Kp) {
    int i = blockIdx.x * blockDim.x + threadIdx.x;
    if (i >= Nr * Kp) return;
    int r = i / Kp, c = i - r * Kp;
    dst[i] = (c < Kin) ? rtf32(src[(size_t)r * Kin + c]) : 0.f;
}

// ---------------- u reduction ----------------
__global__ void k_ur(const float* __restrict__ u, const float* __restrict__ w,
                     const float* __restrict__ bias, int B) {
    int wid = (blockIdx.x * blockDim.x + threadIdx.x) >> 5;
    int lane = threadIdx.x & 31;
    if (wid >= B * URED) return;
    int b = wid >> 8;
    int j = wid & 255;
    const float* up = u + (size_t)b * USZ;
    const float* wp = w + (size_t)j * USZ;
    float s = 0.f;
    for (int k = lane; k < USZ; k += 32) s += up[k] * wp[k];
    #pragma unroll
    for (int o = 16; o; o >>= 1) s += __shfl_down_sync(0xffffffffu, s, o);
    if (lane == 0) g_ur[wid] = rtf32(s + bias[j]);
}

// ---------------- edge input concat (rounded, padded) ----------------
__global__ void k_econcat(const float* __restrict__ x, const void* __restrict__ eidx,
                          const float* __restrict__ ea, const void* __restrict__ batch,
                          int E) {
    int e = (blockIdx.x * blockDim.x + threadIdx.x) >> 5;
    int lane = threadIdx.x & 31;
    if (e >= E) return;
    long long row = ld_idx(eidx, e);
    long long col = ld_idx(eidx, (long long)E + e);
    long long b = ld_idx(batch, row);
    float* o = g_ein + (size_t)e * EINP;
    if (lane < 9)       o[lane] = rtf32(x[row * 9 + lane]);
    else if (lane < 18) o[lane] = rtf32(x[col * 9 + (lane - 9)]);
    else if (lane == 18) o[18]  = rtf32(ea[e]);
    const float* ur = g_ur + b * URED;
    for (int j = lane; j < URED; j += 32) o[19 + j] = ur[j];  // already tf32
    if (lane < EINP - EIN_DIM) o[EIN_DIM + lane] = 0.f;
}

// ---------------- node input concat ----------------
__global__ void k_nconcat(const float* __restrict__ x, const void* __restrict__ eidx,
                          const float* __restrict__ eout, int E) {
    int e = (blockIdx.x * blockDim.x + threadIdx.x) >> 5;
    int lane = threadIdx.x & 31;
    if (e >= E) return;
    long long col = ld_idx(eidx, (long long)E + e);
    float* o = g_nin + (size_t)e * NINP;
    if (lane < 9) o[lane] = rtf32(x[col * 9 + lane]);
    const float* ep = eout + (size_t)e * EOUT;
    for (int j = lane; j < EOUT; j += 32) o[9 + j] = ep[j];   // already tf32
    if (lane < NINP - NIN_DIM) o[NIN_DIM + lane] = 0.f;
}

// ---------------- tf32 tensor-core GEMM ----------------
// C[M,N] = act(A[M,K] @ W[N,K]^T + bias); A pitch = K, W pitch = K, C pitch = N.
// All inputs pre-rounded to tf32 values stored as fp32.
// CTA tile 128x128x32, 8 warps (4M x 2N), warp tile 32x64, double-buffered cp.async.
#define SROW 36                         // smem row stride (conflict-free: 36 mod 32 = 4)
#define SBUF (128 * SROW)               // floats per buffer
#define SMEM_BYTES (4 * SBUF * 4)       // 2 bufs A + 2 bufs B

__device__ __forceinline__ void mma8(float* d, const uint32_t* a, const uint32_t* b) {
    asm volatile(
        "mma.sync.aligned.m16n8k8.row.col.f32.tf32.tf32.f32 "
        "{%0,%1,%2,%3}, {%4,%5,%6,%7}, {%8,%9}, {%0,%1,%2,%3};"
        : "+f"(d[0]), "+f"(d[1]), "+f"(d[2]), "+f"(d[3])
        : "r"(a[0]), "r"(a[1]), "r"(a[2]), "r"(a[3]), "r"(b[0]), "r"(b[1]));
}

template <bool RELU>
__global__ void __launch_bounds__(256)
k_mma(const float* __restrict__ A, const float* __restrict__ W,
      const float* __restrict__ bias, float* __restrict__ C,
      int M, int N, int K) {
    extern __shared__ float smem[];
    float* As = smem;              // [2][128][SROW]
    float* Bs = smem + 2 * SBUF;   // [2][128][SROW]
    const uint32_t s_as = (uint32_t)__cvta_generic_to_shared(As);
    const uint32_t s_bs = (uint32_t)__cvta_generic_to_shared(Bs);

    const int tid = threadIdx.x;
    const int lane = tid & 31, wid = tid >> 5;
    const int warpM = wid & 3, warpN = wid >> 2;
    const int g = lane >> 2, c4 = lane & 3;
    const size_t bm = (size_t)blockIdx.y * 128;
    const int bn = blockIdx.x * 128;

    const int mr = tid >> 3;       // 0..31 (row group for copies)
    const int kc = tid & 7;        // 16B chunk within 32-float row

    float acc[2][8][4];
    #pragma unroll
    for (int i = 0; i < 2; i++)
        #pragma unroll
        for (int j = 0; j < 8; j++)
            #pragma unroll
            for (int r = 0; r < 4; r++) acc[i][j][r] = 0.f;

    const int nk = K >> 5;

    auto copy_stage = [&](int kb, int buf) {
        const int k0 = kb * 32;
        #pragma unroll
        for (int i = 0; i < 4; i++) {
            int m = i * 32 + mr;
            size_t mg = bm + m;
            int bytes = (mg < (size_t)M) ? 16 : 0;
            const float* src = A + (mg < (size_t)M ? mg : 0) * K + k0 + kc * 4;
            uint32_t dst = s_as + (uint32_t)(buf * SBUF + m * SROW + kc * 4) * 4;
            asm volatile("cp.async.cg.shared.global [%0], [%1], 16, %2;"
                         :: "r"(dst), "l"(src), "r"(bytes));
        }
        #pragma unroll
        for (int i = 0; i < 4; i++) {
            int n = i * 32 + mr;
            const float* src = W + (size_t)(bn + n) * K + k0 + kc * 4;
            uint32_t dst = s_bs + (uint32_t)(buf * SBUF + n * SROW + kc * 4) * 4;
            asm volatile("cp.async.cg.shared.global [%0], [%1], 16;"
                         :: "r"(dst), "l"(src));
        }
        asm volatile("cp.async.commit_group;" ::: "memory");
    };

    copy_stage(0, 0);

    for (int kb = 0; kb < nk; kb++) {
        asm volatile("cp.async.wait_group 0;" ::: "memory");
        __syncthreads();
        if (kb + 1 < nk) copy_stage(kb + 1, (kb + 1) & 1);

        const uint32_t* Ab = reinterpret_cast<const uint32_t*>(As + (kb & 1) * SBUF);
        const uint32_t* Bb = reinterpret_cast<const uint32_t*>(Bs + (kb & 1) * SBUF);

        #pragma unroll
        for (int s = 0; s < 4; s++) {
            const int ko = s * 8;
            uint32_t a[2][4], b[8][2];
            #pragma unroll
            for (int mt = 0; mt < 2; mt++) {
                int r0 = warpM * 32 + mt * 16 + g;
                a[mt][0] = Ab[r0 * SROW + ko + c4];
                a[mt][1] = Ab[(r0 + 8) * SROW + ko + c4];
                a[mt][2] = Ab[r0 * SROW + ko + c4 + 4];
                a[mt][3] = Ab[(r0 + 8) * SROW + ko + c4 + 4];
            }
            #pragma unroll
            for (int nt = 0; nt < 8; nt++) {
                int n0 = warpN * 64 + nt * 8 + g;
                b[nt][0] = Bb[n0 * SROW + ko + c4];
                b[nt][1] = Bb[n0 * SROW + ko + c4 + 4];
            }
            #pragma unroll
            for (int mt = 0; mt < 2; mt++)
                #pragma unroll
                for (int nt = 0; nt < 8; nt++)
                    mma8(acc[mt][nt], a[mt], b[nt]);
        }
        __syncthreads();
    }

    // epilogue: bias + relu + tf32 round, float2 stores
    #pragma unroll
    for (int mt = 0; mt < 2; mt++) {
        size_t r0 = bm + warpM * 32 + mt * 16 + g;
        #pragma unroll
        for (int nt = 0; nt < 8; nt++) {
            int col = bn + warpN * 64 + nt * 8 + 2 * c4;
            float b0 = bias[col], b1 = bias[col + 1];
            float v0 = acc[mt][nt][0] + b0, v1 = acc[mt][nt][1] + b1;
            float v2 = acc[mt][nt][2] + b0, v3 = acc[mt][nt][3] + b1;
            if (RELU) {
                v0 = v0 > 0.f ? v0 : 0.f; v1 = v1 > 0.f ? v1 : 0.f;
                v2 = v2 > 0.f ? v2 : 0.f; v3 = v3 > 0.f ? v3 : 0.f;
            }
            v0 = rtf32(v0); v1 = rtf32(v1); v2 = rtf32(v2); v3 = rtf32(v3);
            if (r0 < (size_t)M)
                *reinterpret_cast<float2*>(C + r0 * N + col) = make_float2(v0, v1);
            if (r0 + 8 < (size_t)M)
                *reinterpret_cast<float2*>(C + (r0 + 8) * N + col) = make_float2(v2, v3);
        }
    }
}

// ---------------- zero fill ----------------
__global__ void k_zero(float* p, int n) {
    int i = blockIdx.x * blockDim.x + threadIdx.x;
    if (i < n) p[i] = 0.f;
}

// ---------------- scatter-add ----------------
__global__ void k_scatter(const float* __restrict__ h, const void* __restrict__ eidx, int E) {
    int e = (blockIdx.x * blockDim.x + threadIdx.x) >> 5;
    int lane = threadIdx.x & 31;
    if (e >= E) return;
    long long r = ld_idx(eidx, e);
    float* a = g_agg + (size_t)r * NH;
    const float* hp = h + (size_t)e * NH;
    for (int j = lane; j < NH; j += 32) atomicAdd(&a[j], hp[j]);
    if (lane == 0) atomicAdd(&g_cnt[r], 1.f);
}

// ---------------- final node concat ----------------
__global__ void k_mconcat(const float* __restrict__ x, const void* __restrict__ batch, int Nn) {
    int n = (blockIdx.x * blockDim.x + threadIdx.x) >> 5;
    int lane = threadIdx.x & 31;
    if (n >= Nn) return;
    float* o = g_min + (size_t)n * MINP;
    if (lane < 9) o[lane] = rtf32(x[(size_t)n * 9 + lane]);
    float c = g_cnt[n];
    float inv = 1.f / (c < 1.f ? 1.f : c);
    const float* a = g_agg + (size_t)n * NH;
    for (int j = lane; j < NH; j += 32) o[9 + j] = rtf32(a[j] * inv);
    long long b = ld_idx(batch, n);
    const float* ur = g_ur + b * URED;
    for (int j = lane; j < URED; j += 32) o[9 + NH + j] = ur[j];
    if (lane < MINP - MIN_DIM) o[MIN_DIM + lane] = 0.f;
}

// ---------------- final 512 -> 1 dot (fp32 exact) ----------------
__global__ void k_final(const float* __restrict__ h, const float* __restrict__ w,
                        const float* __restrict__ bias, float* __restrict__ out, int Nn) {
    int n = (blockIdx.x * blockDim.x + threadIdx.x) >> 5;
    int lane = threadIdx.x & 31;
    if (n >= Nn) return;
    const float* hp = h + (size_t)n * NH;
    float s = 0.f;
    for (int k = lane; k < NH; k += 32) s += hp[k] * w[k];
    #pragma unroll
    for (int o = 16; o; o >>= 1) s += __shfl_down_sync(0xffffffffu, s, o);
    if (lane == 0) out[n] = s + bias[0];
}

// ---------------- host helpers ----------------
static float* sym(const void* s) {
    void* p = nullptr;
    cudaGetSymbolAddress(&p, s);
    return (float*)p;
}

static void run_mma(const float* A, const float* W, const float* bias, float* C,
                    int M, int N, int K, bool relu) {
    dim3 grid(N / 128, (M + 127) / 128);
    if (relu) k_mma<true><<<grid, 256, SMEM_BYTES>>>(A, W, bias, C, M, N, K);
    else      k_mma<false><<<grid, 256, SMEM_BYTES>>>(A, W, bias, C, M, N, K);
}

static void repack(const float* src, float* dst, int Nr, int Kin, int Kp) {
    int tot = Nr * Kp;
    k_repack<<<(tot + 255) / 256, 256>>>(src, dst, Nr, Kin, Kp);
}

extern "C" void kernel_launch(void* const* d_in, const int* in_sizes, int n_in,
                              void* d_out, int out_size) {
    const float* x    = (const float*)d_in[0];
    const void*  eidx = d_in[1];
    const float* ea   = (const float*)d_in[2];
    const float* u    = (const float*)d_in[3];
    const void*  bat  = d_in[4];
    const float* w_sel = (const float*)d_in[5];
    const float* b_sel = (const float*)d_in[6];
    const float* ew0 = (const float*)d_in[7];  const float* eb0 = (const float*)d_in[8];
    const float* ew1 = (const float*)d_in[9];  const float* eb1 = (const float*)d_in[10];
    const float* ew2 = (const float*)d_in[11]; const float* eb2 = (const float*)d_in[12];
    const float* ew3 = (const float*)d_in[13]; const float* eb3 = (const float*)d_in[14];
    const float* ew4 = (const float*)d_in[15]; const float* eb4 = (const float*)d_in[16];
    const float* nw0 = (const float*)d_in[17]; const float* nb0 = (const float*)d_in[18];
    const float* nw1 = (const float*)d_in[19]; const float* nb1 = (const float*)d_in[20];
    const float* mw0 = (const float*)d_in[21]; const float* mb0 = (const float*)d_in[22];
    const float* mw1 = (const float*)d_in[23]; const float* mb1 = (const float*)d_in[24];
    float* out = (float*)d_out;

    const int Nn = in_sizes[0] / 9;
    const int E  = in_sizes[1] / 2;
    const int B  = in_sizes[3] / USZ;

    float* p_ur  = sym(g_ur);  (void)p_ur;
    float* p_ein = sym(g_ein);
    float* p_h1  = sym(g_h1);
    float* p_h2  = sym(g_h2);
    float* p_nin = sym(g_nin);
    float* p_agg = sym(g_agg);
    float* p_cnt = sym(g_cnt);
    float* p_min = sym(g_min);
    float* p_w0 = sym(g_w0); float* p_w1 = sym(g_w1); float* p_w2 = sym(g_w2);
    float* p_w3 = sym(g_w3); float* p_w4 = sym(g_w4);
    float* p_wn0 = sym(g_wn0); float* p_wn1 = sym(g_wn1); float* p_wm0 = sym(g_wm0);

    cudaFuncSetAttribute(k_mma<true>,  cudaFuncAttributeMaxDynamicSharedMemorySize, SMEM_BYTES);
    cudaFuncSetAttribute(k_mma<false>, cudaFuncAttributeMaxDynamicSharedMemorySize, SMEM_BYTES);

    // 0. dtype detection
    k_init_flag<<<1, 1>>>();
    k_detect<<<(E + 255) / 256, 256>>>((const long long*)eidx, E, (long long)Nn);

    // 0b. weight repack (pad + tf32 round)
    repack(ew0, p_w0, EH, EIN_DIM, EINP);
    repack(ew1, p_w1, EH, EH, EH);
    repack(ew2, p_w2, EH, EH, EH);
    repack(ew3, p_w3, EH, EH, EH);
    repack(ew4, p_w4, EOUT, EH, EH);
    repack(nw0, p_wn0, NH, NIN_DIM, NINP);
    repack(nw1, p_wn1, NH, NH, NH);
    repack(mw0, p_wm0, NH, MIN_DIM, MINP);

    // 1. u_r
    k_ur<<<(B * URED * 32 + 255) / 256, 256>>>(u, w_sel, b_sel, B);

    // 2. edge input concat
    k_econcat<<<(E * 32 + 255) / 256, 256>>>(x, eidx, ea, bat, E);

    // 3. edge MLP
    run_mma(p_ein, p_w0, eb0, p_h1, E, EH, EINP, true);
    run_mma(p_h1,  p_w1, eb1, p_h2, E, EH, EH, true);
    run_mma(p_h2,  p_w2, eb2, p_h1, E, EH, EH, true);
    run_mma(p_h1,  p_w3, eb3, p_h2, E, EH, EH, true);
    run_mma(p_h2,  p_w4, eb4, p_h1, E, EOUT, EH, false);

    // 4. node input concat
    k_nconcat<<<(E * 32 + 255) / 256, 256>>>(x, eidx, p_h1, E);

    // 5. node MLP1
    run_mma(p_nin, p_wn0, nb0, p_h2, E, NH, NINP, true);
    run_mma(p_h2,  p_wn1, nb1, p_h1, E, NH, NH, true);

    // 6. scatter mean
    k_zero<<<(Nn * NH + 255) / 256, 256>>>(p_agg, Nn * NH);
    k_zero<<<(Nn + 255) / 256, 256>>>(p_cnt, Nn);
    k_scatter<<<(E * 32 + 255) / 256, 256>>>(p_h1, eidx, E);

    // 7. final concat
    k_mconcat<<<(Nn * 32 + 255) / 256, 256>>>(x, bat, Nn);

    // 8. node MLP2 + final dot
    run_mma(p_min, p_wm0, mb0, p_h2, Nn, NH, MINP, true);
    k_final<<<(Nn * 32 + 255) / 256, 256>>>(p_h2, mw1, mb1, out, Nn);
}

// round 9
// speedup vs baseline: 13.1931x; 2.8704x over previous
#include <cuda_runtime.h>
#include <cuda_fp16.h>
#include <cstdint>

// ---------------- Problem constants ----------------
#define EMAX 100000
#define NNMAX 20000
#define BMAX 16
#define URED 256
#define USZ 4096
#define EIN_DIM 275
#define EINP 320          // padded to x64
#define EH 1024
#define EOUT 512
#define NIN_DIM 521
#define NINP 576          // padded
#define NH 512
#define MIN_DIM 777
#define MINP 832          // padded

// ---------------- Scratch (static device globals) ----------------
__device__ __align__(16) __half g_ur[BMAX * URED];
__device__ __align__(16) __half g_ein[(size_t)EMAX * EINP];
__device__ __align__(16) __half g_ha[(size_t)EMAX * EH];
__device__ __align__(16) __half g_hb[(size_t)EMAX * EH];
__device__ __align__(16) __half g_nin[(size_t)EMAX * NINP];
__device__ __align__(16) float  g_agg[(size_t)NNMAX * NH];
__device__ float g_cnt[NNMAX];
__device__ __align__(16) __half g_min[(size_t)NNMAX * MINP];
__device__ int   g_is64;

// repacked fp16 weights (zero-padded, column-permuted to match concat layouts)
__device__ __align__(16) __half g_w0[EH * EINP];
__device__ __align__(16) __half g_w1[EH * EH];
__device__ __align__(16) __half g_w2[EH * EH];
__device__ __align__(16) __half g_w3[EH * EH];
__device__ __align__(16) __half g_w4[EOUT * EH];
__device__ __align__(16) __half g_wn0[NH * NINP];
__device__ __align__(16) __half g_wn1[NH * NH];
__device__ __align__(16) __half g_wm0[NH * MINP];

// ---------------- helpers ----------------
__device__ __forceinline__ uint32_t smem_u32(const void* p) {
    uint32_t a;
    asm("{ .reg .u64 t; cvta.to.shared.u64 t, %1; cvt.u32.u64 %0, t; }" : "=r"(a) : "l"(p));
    return a;
}
__device__ __forceinline__ uint32_t sw128(uint32_t off) { return off ^ ((off >> 3) & 0x70); }

// ---------------- Index dtype detection ----------------
__global__ void k_init_flag() { g_is64 = 1; }
__global__ void k_detect(const long long* __restrict__ p, int n, long long maxv) {
    int i = blockIdx.x * blockDim.x + threadIdx.x;
    if (i < n) { long long v = p[i]; if (v < 0 || v >= maxv) g_is64 = 0; }
}
__device__ __forceinline__ long long ld_idx(const void* p, long long i) {
    if (g_is64) return ((const long long*)p)[i];
    return (long long)((const int*)p)[i];
}

// ---------------- weight repack: fp16 + pad + column permutation ----------------
__global__ void k_repackp(const float* __restrict__ src, __half* __restrict__ dst,
                          int Nr, int Kin, int Kp,
                          int l0, int s0, int l1, int s1, int l2, int s2, int l3, int s3) {
    int i = blockIdx.x * blockDim.x + threadIdx.x;
    if (i >= Nr * Kp) return;
    int r = i / Kp, c = i - r * Kp;
    int sc = -1;
    if (c < l0) sc = s0 + c;
    else if (c < l0 + l1) sc = s1 + (c - l0);
    else if (c < l0 + l1 + l2) sc = s2 + (c - l0 - l1);
    else if (c < l0 + l1 + l2 + l3) sc = s3 + (c - l0 - l1 - l2);
    dst[i] = (sc >= 0) ? __float2half_rn(src[(size_t)r * Kin + sc]) : __half(0.f);
}

// ---------------- u reduction ----------------
__global__ void k_ur(const float* __restrict__ u, const float* __restrict__ w,
                     const float* __restrict__ bias, int B) {
    int wid = (blockIdx.x * blockDim.x + threadIdx.x) >> 5;
    int lane = threadIdx.x & 31;
    if (wid >= B * URED) return;
    int b = wid >> 8, j = wid & 255;
    const float* up = u + (size_t)b * USZ;
    const float* wp = w + (size_t)j * USZ;
    float s = 0.f;
    for (int k = lane; k < USZ; k += 32) s += up[k] * wp[k];
    #pragma unroll
    for (int o = 16; o; o >>= 1) s += __shfl_down_sync(0xffffffffu, s, o);
    if (lane == 0) g_ur[wid] = __float2half_rn(s + bias[j]);
}

// ---------------- edge concat: layout [ur(256) | x_row(9) | x_col(9) | ea(1) | pad] ----------------
__global__ void k_econcat(const float* __restrict__ x, const void* __restrict__ eidx,
                          const float* __restrict__ ea, const void* __restrict__ batch, int E) {
    int e = (blockIdx.x * blockDim.x + threadIdx.x) >> 5;
    int lane = threadIdx.x & 31;
    if (e >= E) return;
    long long row = ld_idx(eidx, e);
    long long col = ld_idx(eidx, (long long)E + e);
    long long b = ld_idx(batch, row);
    __half* o = g_ein + (size_t)e * EINP;
    const uint4* urv = (const uint4*)(g_ur + b * URED);
    ((uint4*)o)[lane] = urv[lane];                       // 256 halves
    if (lane < 9)       o[256 + lane] = __float2half_rn(x[row * 9 + lane]);
    else if (lane < 18) o[256 + lane] = __float2half_rn(x[col * 9 + (lane - 9)]);
    else if (lane == 18) o[274] = __float2half_rn(ea[e]);
    for (int j = EIN_DIM + lane; j < EINP; j += 32) o[j] = __half(0.f);
}

// ---------------- node concat: layout [edge_out(512) | x_col(9) | pad] ----------------
__global__ void k_nconcat(const float* __restrict__ x, const void* __restrict__ eidx,
                          const __half* __restrict__ eout, int E) {
    int e = (blockIdx.x * blockDim.x + threadIdx.x) >> 5;
    int lane = threadIdx.x & 31;
    if (e >= E) return;
    long long col = ld_idx(eidx, (long long)E + e);
    __half* o = g_nin + (size_t)e * NINP;
    const uint4* ev = (const uint4*)(eout + (size_t)e * EOUT);
    ((uint4*)o)[lane] = ev[lane];
    ((uint4*)o)[lane + 32] = ev[lane + 32];
    if (lane < 9) o[512 + lane] = __float2half_rn(x[col * 9 + lane]);
    for (int j = NIN_DIM + lane; j < NINP; j += 32) o[j] = __half(0.f);
}

// ---------------- fp16 mma.sync GEMM ----------------
// C[M,Ntot] = act(A[M,K] @ W[Ntot,K]^T + bias), fp16 in/out, fp32 accum.
// CTA tile 128x128, K staged 64 halves (128B rows, SW128). 8 warps: 4M x 2N, warp 32x64.
#define HTILE 16384                       // bytes per tile (128 rows x 128B)
#define H_SMEM (4 * HTILE)                // A[2] + B[2]

__device__ __forceinline__ void ldm4(uint32_t* r, uint32_t addr) {
    asm volatile("ldmatrix.sync.aligned.m8n8.x4.shared.b16 {%0,%1,%2,%3}, [%4];"
                 : "=r"(r[0]), "=r"(r[1]), "=r"(r[2]), "=r"(r[3]) : "r"(addr));
}
__device__ __forceinline__ void mma16(float* d, const uint32_t* a, const uint32_t* b) {
    asm volatile(
        "mma.sync.aligned.m16n8k16.row.col.f32.f16.f16.f32 "
        "{%0,%1,%2,%3}, {%4,%5,%6,%7}, {%8,%9}, {%0,%1,%2,%3};"
        : "+f"(d[0]), "+f"(d[1]), "+f"(d[2]), "+f"(d[3])
        : "r"(a[0]), "r"(a[1]), "r"(a[2]), "r"(a[3]), "r"(b[0]), "r"(b[1]));
}

template <bool RELU>
__global__ void __launch_bounds__(256)
k_hmma(const __half* __restrict__ A, const __half* __restrict__ W,
       const float* __restrict__ bias, __half* __restrict__ C,
       int M, int Ntot, int K) {
    extern __shared__ char smem[];
    const uint32_t s_as = smem_u32(smem);
    const uint32_t s_bs = s_as + 2 * HTILE;

    const int tid = threadIdx.x;
    const int lane = tid & 31, wid = tid >> 5;
    const int warpM = wid & 3, warpN = wid >> 2;
    const size_t bm = (size_t)blockIdx.y * 128;
    const int bn = blockIdx.x * 128;
    const int nk = K >> 6;                // stages of 64 halves

    // copy mapping: 16B chunk cc (0..7) within 128B row, row group r0 (0..31)
    const int cc = tid & 7, r0 = tid >> 3;

    // ldmatrix lane addressing (byte offsets within tile, pre-swizzle)
    const int a_row = warpM * 32 + (lane & 15);          // + mt*16
    const int a_kb  = (lane >> 4) * 16;                  // 0 or 16 bytes
    const int b_row = warpN * 64 + ((lane >> 4) << 3) + (lane & 7);  // + p*16
    const int b_kb  = ((lane >> 3) & 1) * 16;

    float acc[2][8][4];
    #pragma unroll
    for (int i = 0; i < 2; i++)
        #pragma unroll
        for (int j = 0; j < 8; j++)
            #pragma unroll
            for (int r = 0; r < 4; r++) acc[i][j][r] = 0.f;

    auto copy_stage = [&](int kb, int buf) {
        const int kB = kb * 128;                         // byte offset along K
        #pragma unroll
        for (int i = 0; i < 4; i++) {
            int r = r0 + i * 32;
            size_t mg = bm + r;
            int ok = (mg < (size_t)M) ? 16 : 0;
            const char* src = (const char*)(A + (mg < (size_t)M ? mg : 0) * K) + kB + cc * 16;
            uint32_t dst = s_as + buf * HTILE + sw128(r * 128 + cc * 16);
            asm volatile("cp.async.cg.shared.global [%0], [%1], 16, %2;"
                         :: "r"(dst), "l"(src), "r"(ok));
        }
        #pragma unroll
        for (int i = 0; i < 4; i++) {
            int r = r0 + i * 32;
            const char* src = (const char*)(W + (size_t)(bn + r) * K) + kB + cc * 16;
            uint32_t dst = s_bs + buf * HTILE + sw128(r * 128 + cc * 16);
            asm volatile("cp.async.cg.shared.global [%0], [%1], 16;" :: "r"(dst), "l"(src));
        }
        asm volatile("cp.async.commit_group;" ::: "memory");
    };

    copy_stage(0, 0);

    for (int kb = 0; kb < nk; kb++) {
        asm volatile("cp.async.wait_group 0;" ::: "memory");
        __syncthreads();
        if (kb + 1 < nk) copy_stage(kb + 1, (kb + 1) & 1);

        const uint32_t Ab = s_as + (kb & 1) * HTILE;
        const uint32_t Bb = s_bs + (kb & 1) * HTILE;

        #pragma unroll
        for (int s = 0; s < 4; s++) {                    // 4 x K=16 per stage
            const int ks = s * 32;                       // byte offset along K
            uint32_t a[2][4];
            #pragma unroll
            for (int mt = 0; mt < 2; mt++)
                ldm4(a[mt], Ab + sw128((a_row + mt * 16) * 128 + ks + a_kb));
            #pragma unroll
            for (int p = 0; p < 4; p++) {
                uint32_t b[4];
                ldm4(b, Bb + sw128((b_row + p * 16) * 128 + ks + b_kb));
                #pragma unroll
                for (int mt = 0; mt < 2; mt++) {
                    mma16(acc[mt][2 * p],     a[mt], b);
                    mma16(acc[mt][2 * p + 1], a[mt], b + 2);
                }
            }
        }
        __syncthreads();
    }

    // epilogue: bias + relu, fp16 (half2) stores
    const int qrow = lane >> 2, qcol = (lane & 3) * 2;
    #pragma unroll
    for (int mt = 0; mt < 2; mt++) {
        size_t r0g = bm + warpM * 32 + mt * 16 + qrow;
        #pragma unroll
        for (int nt = 0; nt < 8; nt++) {
            int col = bn + warpN * 64 + nt * 8 + qcol;
            float b0 = bias[col], b1 = bias[col + 1];
            float v0 = acc[mt][nt][0] + b0, v1 = acc[mt][nt][1] + b1;
            float v2 = acc[mt][nt][2] + b0, v3 = acc[mt][nt][3] + b1;
            if (RELU) {
                v0 = v0 > 0.f ? v0 : 0.f; v1 = v1 > 0.f ? v1 : 0.f;
                v2 = v2 > 0.f ? v2 : 0.f; v3 = v3 > 0.f ? v3 : 0.f;
            }
            if (r0g < (size_t)M)
                *(__half2*)(C + r0g * Ntot + col) = __floats2half2_rn(v0, v1);
            if (r0g + 8 < (size_t)M)
                *(__half2*)(C + (r0g + 8) * Ntot + col) = __floats2half2_rn(v2, v3);
        }
    }
}

// ---------------- zero fill ----------------
__global__ void k_zero(float* p, int n) {
    int i = blockIdx.x * blockDim.x + threadIdx.x;
    if (i < n) p[i] = 0.f;
}

// ---------------- scatter-add (float4 atomics) ----------------
__global__ void k_scatter(const __half* __restrict__ h, const void* __restrict__ eidx, int E) {
    int e = (blockIdx.x * blockDim.x + threadIdx.x) >> 5;
    int lane = threadIdx.x & 31;
    if (e >= E) return;
    long long r = ld_idx(eidx, e);
    float4* a = (float4*)(g_agg + (size_t)r * NH);
    const __half2* hp = (const __half2*)(h + (size_t)e * NH);
    #pragma unroll
    for (int i = 0; i < 4; i++) {
        int j = lane + i * 32;
        float2 f0 = __half22float2(hp[2 * j]);
        float2 f1 = __half22float2(hp[2 * j + 1]);
        atomicAdd(a + j, make_float4(f0.x, f0.y, f1.x, f1.y));
    }
    if (lane == 0) atomicAdd(&g_cnt[r], 1.f);
}

// ---------------- final concat: layout [agg(512) | ur(256) | x(9) | pad] ----------------
__global__ void k_mconcat(const float* __restrict__ x, const void* __restrict__ batch, int Nn) {
    int n = (blockIdx.x * blockDim.x + threadIdx.x) >> 5;
    int lane = threadIdx.x & 31;
    if (n >= Nn) return;
    __half* o = g_min + (size_t)n * MINP;
    float c = g_cnt[n];
    float inv = 1.f / (c < 1.f ? 1.f : c);
    const float2* a = (const float2*)(g_agg + (size_t)n * NH);
    for (int j = lane; j < 256; j += 32) {
        float2 v = a[j];
        ((__half2*)o)[j] = __floats2half2_rn(v.x * inv, v.y * inv);
    }
    long long b = ld_idx(batch, n);
    const uint4* urv = (const uint4*)(g_ur + b * URED);
    ((uint4*)(o + 512))[lane] = urv[lane];
    if (lane < 9) o[768 + lane] = __float2half_rn(x[(size_t)n * 9 + lane]);
    for (int j = MIN_DIM + lane; j < MINP; j += 32) o[j] = __half(0.f);
}

// ---------------- final 512 -> 1 dot (fp32) ----------------
__global__ void k_final(const __half* __restrict__ h, const float* __restrict__ w,
                        const float* __restrict__ bias, float* __restrict__ out, int Nn) {
    int n = (blockIdx.x * blockDim.x + threadIdx.x) >> 5;
    int lane = threadIdx.x & 31;
    if (n >= Nn) return;
    const __half* hp = h + (size_t)n * NH;
    float s = 0.f;
    for (int k = lane; k < NH; k += 32) s += __half2float(hp[k]) * w[k];
    #pragma unroll
    for (int o = 16; o; o >>= 1) s += __shfl_down_sync(0xffffffffu, s, o);
    if (lane == 0) out[n] = s + bias[0];
}

// ---------------- host ----------------
static void* sym(const void* s) { void* p = nullptr; cudaGetSymbolAddress(&p, s); return p; }

static void run_hmma(const __half* A, const __half* W, const float* bias, __half* C,
                     int M, int Ntot, int K, bool relu) {
    dim3 grid(Ntot / 128, (M + 127) / 128);
    if (relu) k_hmma<true><<<grid, 256, H_SMEM>>>(A, W, bias, C, M, Ntot, K);
    else      k_hmma<false><<<grid, 256, H_SMEM>>>(A, W, bias, C, M, Ntot, K);
}

static void repackp(const float* src, __half* dst, int Nr, int Kin, int Kp,
                    int l0, int s0, int l1 = 0, int s1 = 0, int l2 = 0, int s2 = 0,
                    int l3 = 0, int s3 = 0) {
    int tot = Nr * Kp;
    k_repackp<<<(tot + 255) / 256, 256>>>(src, dst, Nr, Kin, Kp, l0, s0, l1, s1, l2, s2, l3, s3);
}

extern "C" void kernel_launch(void* const* d_in, const int* in_sizes, int n_in,
                              void* d_out, int out_size) {
    const float* x    = (const float*)d_in[0];
    const void*  eidx = d_in[1];
    const float* ea   = (const float*)d_in[2];
    const float* u    = (const float*)d_in[3];
    const void*  bat  = d_in[4];
    const float* w_sel = (const float*)d_in[5];
    const float* b_sel = (const float*)d_in[6];
    const float* ew0 = (const float*)d_in[7];  const float* eb0 = (const float*)d_in[8];
    const float* ew1 = (const float*)d_in[9];  const float* eb1 = (const float*)d_in[10];
    const float* ew2 = (const float*)d_in[11]; const float* eb2 = (const float*)d_in[12];
    const float* ew3 = (const float*)d_in[13]; const float* eb3 = (const float*)d_in[14];
    const float* ew4 = (const float*)d_in[15]; const float* eb4 = (const float*)d_in[16];
    const float* nw0 = (const float*)d_in[17]; const float* nb0 = (const float*)d_in[18];
    const float* nw1 = (const float*)d_in[19]; const float* nb1 = (const float*)d_in[20];
    const float* mw0 = (const float*)d_in[21]; const float* mb0 = (const float*)d_in[22];
    const float* mw1 = (const float*)d_in[23]; const float* mb1 = (const float*)d_in[24];
    float* out = (float*)d_out;

    const int Nn = in_sizes[0] / 9;
    const int E  = in_sizes[1] / 2;
    const int B  = in_sizes[3] / USZ;

    __half* p_ein = (__half*)sym(g_ein);
    __half* p_ha  = (__half*)sym(g_ha);
    __half* p_hb  = (__half*)sym(g_hb);
    __half* p_nin = (__half*)sym(g_nin);
    __half* p_min = (__half*)sym(g_min);
    float*  p_agg = (float*)sym(g_agg);
    float*  p_cnt = (float*)sym(g_cnt);
    __half* p_w0 = (__half*)sym(g_w0); __half* p_w1 = (__half*)sym(g_w1);
    __half* p_w2 = (__half*)sym(g_w2); __half* p_w3 = (__half*)sym(g_w3);
    __half* p_w4 = (__half*)sym(g_w4);
    __half* p_wn0 = (__half*)sym(g_wn0); __half* p_wn1 = (__half*)sym(g_wn1);
    __half* p_wm0 = (__half*)sym(g_wm0);

    cudaFuncSetAttribute(k_hmma<true>,  cudaFuncAttributeMaxDynamicSharedMemorySize, H_SMEM);
    cudaFuncSetAttribute(k_hmma<false>, cudaFuncAttributeMaxDynamicSharedMemorySize, H_SMEM);

    // 0. dtype detect + weight repack (fp16, padded, permuted to concat layouts)
    k_init_flag<<<1, 1>>>();
    k_detect<<<(E + 255) / 256, 256>>>((const long long*)eidx, E, (long long)Nn);

    repackp(ew0, p_w0, EH, EIN_DIM, EINP, 256, 19, 9, 0, 9, 9, 1, 18);  // [ur|xr|xc|ea]
    repackp(ew1, p_w1, EH, EH, EH, EH, 0);
    repackp(ew2, p_w2, EH, EH, EH, EH, 0);
    repackp(ew3, p_w3, EH, EH, EH, EH, 0);
    repackp(ew4, p_w4, EOUT, EH, EH, EH, 0);
    repackp(nw0, p_wn0, NH, NIN_DIM, NINP, 512, 9, 9, 0);               // [eout|xc]
    repackp(nw1, p_wn1, NH, NH, NH, NH, 0);
    repackp(mw0, p_wm0, NH, MIN_DIM, MINP, 512, 9, 256, 521, 9, 0);     // [agg|ur|x]

    // 1. u_r
    k_ur<<<(B * URED * 32 + 255) / 256, 256>>>(u, w_sel, b_sel, B);

    // 2. edge concat
    k_econcat<<<(E * 32 + 255) / 256, 256>>>(x, eidx, ea, bat, E);

    // 3. edge MLP (fp16 HMMA)
    run_hmma(p_ein, p_w0, eb0, p_ha, E, EH, EINP, true);
    run_hmma(p_ha,  p_w1, eb1, p_hb, E, EH, EH, true);
    run_hmma(p_hb,  p_w2, eb2, p_ha, E, EH, EH, true);
    run_hmma(p_ha,  p_w3, eb3, p_hb, E, EH, EH, true);
    run_hmma(p_hb,  p_w4, eb4, p_ha, E, EOUT, EH, false);   // edge_out, pitch 512

    // 4. node concat
    k_nconcat<<<(E * 32 + 255) / 256, 256>>>(x, eidx, p_ha, E);

    // 5. node MLP1
    run_hmma(p_nin, p_wn0, nb0, p_hb, E, NH, NINP, true);
    run_hmma(p_hb,  p_wn1, nb1, p_ha, E, NH, NH, true);

    // 6. scatter mean
    k_zero<<<(Nn * NH + 255) / 256, 256>>>(p_agg, Nn * NH);
    k_zero<<<(Nn + 255) / 256, 256>>>(p_cnt, Nn);
    k_scatter<<<(E * 32 + 255) / 256, 256>>>(p_ha, eidx, E);

    // 7. final concat
    k_mconcat<<<(Nn * 32 + 255) / 256, 256>>>(x, bat, Nn);

    // 8. node MLP2 + final dot
    run_hmma(p_min, p_wm0, mb0, p_hb, Nn, NH, MINP, true);
    k_final<<<(Nn * 32 + 255) / 256, 256>>>(p_hb, mw1, mb1, out, Nn);
}